// round 3
// baseline (speedup 1.0000x reference)
#include <cuda_runtime.h>
#include <stdint.h>
#include <math.h>

// CounterfactualDiffusion: 50-step diffusion sampler, persistent kernel.
// Each CTA owns MTILE=64 batch rows for all 50 steps (rows are independent).
#define BATCH    8192
#define LAT      128
#define HID      512
#define NSTEPS   50
#define MTILE    64
#define NTHREADS 512
#define NCTAS    (BATCH / MTILE)   // 128
#define ACTSTR   512
#define KCL      16

// ---------------- JAX threefry-2x32 (exact) ----------------
__device__ __forceinline__ uint32_t rotl32(uint32_t x, uint32_t r) {
    return __funnelshift_l(x, x, r);
}

__device__ __forceinline__ void threefry2x32(uint32_t k0, uint32_t k1,
                                             uint32_t c0, uint32_t c1,
                                             uint32_t& o0, uint32_t& o1) {
    uint32_t ks2 = k0 ^ k1 ^ 0x1BD11BDAu;
    uint32_t x0 = c0 + k0;
    uint32_t x1 = c1 + k1;
#define TF_RND(r) { x0 += x1; x1 = rotl32(x1, r); x1 ^= x0; }
    TF_RND(13) TF_RND(15) TF_RND(26) TF_RND(6)
    x0 += k1;  x1 += ks2 + 1u;
    TF_RND(17) TF_RND(29) TF_RND(16) TF_RND(24)
    x0 += ks2; x1 += k0 + 2u;
    TF_RND(13) TF_RND(15) TF_RND(26) TF_RND(6)
    x0 += k0;  x1 += k1 + 3u;
    TF_RND(17) TF_RND(29) TF_RND(16) TF_RND(24)
    x0 += k1;  x1 += ks2 + 4u;
    TF_RND(13) TF_RND(15) TF_RND(26) TF_RND(6)
    x0 += ks2; x1 += k0 + 5u;
#undef TF_RND
    o0 = x0; o1 = x1;
}

// XLA f32 erf_inv (Giles polynomial) — matches lax.erf_inv
__device__ __forceinline__ float erfinv_f32(float x) {
    float w = -log1pf(-x * x);
    float p;
    if (w < 5.0f) {
        w -= 2.5f;
        p = 2.81022636e-08f;
        p = fmaf(p, w, 3.43273939e-07f);
        p = fmaf(p, w, -3.5233877e-06f);
        p = fmaf(p, w, -4.39150654e-06f);
        p = fmaf(p, w, 0.00021858087f);
        p = fmaf(p, w, -0.00125372503f);
        p = fmaf(p, w, -0.00417768164f);
        p = fmaf(p, w, 0.246640727f);
        p = fmaf(p, w, 1.50140941f);
    } else {
        w = sqrtf(w) - 3.0f;
        p = -0.000200214257f;
        p = fmaf(p, w, 0.000100950558f);
        p = fmaf(p, w, 0.00134934322f);
        p = fmaf(p, w, -0.00367342844f);
        p = fmaf(p, w, 0.00573950773f);
        p = fmaf(p, w, -0.0076224613f);
        p = fmaf(p, w, 0.00943887047f);
        p = fmaf(p, w, 1.00167406f);
        p = fmaf(p, w, 2.83297682f);
    }
    return p * x;
}

// JAX partitionable-threefry normal sample for flat element index gi at step t.
// bits = o0 ^ o1 of threefry(folded_key, (0, gi)); u in [-0.99999994, 1);
// normal = sqrt(2) * erfinv(u).
__device__ __forceinline__ float jax_normal(uint32_t fk0, uint32_t fk1, uint32_t gi) {
    uint32_t o0, o1;
    threefry2x32(fk0, fk1, 0u, gi, o0, o1);
    uint32_t bits = o0 ^ o1;
    float f = __uint_as_float((bits >> 9) | 0x3f800000u) - 1.0f;
    // (hi - lo) rounds to exactly 2.0f in f32; mul-by-2 is exact.
    float u = fmaxf(fmaf(f, 2.0f, -0.99999994f), -0.99999994f);
    return 1.4142135623730951f * erfinv_f32(u);
}

__device__ __forceinline__ float gelu_exact(float v) {
    return 0.5f * v * (1.0f + erff(v * 0.7071067811865476f));
}

// ---------------- GEMM micro-tile ----------------
// Each thread: 4 rows (rg*4..+3) x NJ cols (cg + 32*j).  W tile staged in SMEM.
template<int K, int N, int NJ>
__device__ __forceinline__ void dense_layer(const float* __restrict__ W,
                                            const float* sA, float* sW,
                                            float acc[4][NJ],
                                            int tid, int cg, int rg) {
    for (int kb = 0; kb < K; kb += KCL) {
        __syncthreads();
        const float4* gw = reinterpret_cast<const float4*>(W + kb * N);
        float4* sw4 = reinterpret_cast<float4*>(sW);
        constexpr int NVEC = (KCL * N / 4) / NTHREADS;
#pragma unroll
        for (int v = 0; v < NVEC; ++v)
            sw4[v * NTHREADS + tid] = gw[v * NTHREADS + tid];
        __syncthreads();
        const float* a0 = sA + (rg * 4 + 0) * ACTSTR + kb;
        const float* a1 = a0 + ACTSTR;
        const float* a2 = a1 + ACTSTR;
        const float* a3 = a2 + ACTSTR;
#pragma unroll 8
        for (int k = 0; k < KCL; ++k) {
            float v0 = a0[k], v1 = a1[k], v2 = a2[k], v3 = a3[k];
            const float* wr = sW + k * N + cg;
#pragma unroll
            for (int j = 0; j < NJ; ++j) {
                float w = wr[32 * j];
                acc[0][j] = fmaf(v0, w, acc[0][j]);
                acc[1][j] = fmaf(v1, w, acc[1][j]);
                acc[2][j] = fmaf(v2, w, acc[2][j]);
                acc[3][j] = fmaf(v3, w, acc[3][j]);
            }
        }
    }
}

__global__ void __launch_bounds__(NTHREADS, 1)
diffusion_kernel(const float* __restrict__ condition,
                 const float* __restrict__ x_init,
                 const float* __restrict__ W1, const float* __restrict__ b1,
                 const float* __restrict__ W2, const float* __restrict__ b2,
                 const float* __restrict__ W3, const float* __restrict__ b3,
                 const float* __restrict__ W4, const float* __restrict__ b4,
                 const int* __restrict__ tsp,
                 float* __restrict__ out)
{
    extern __shared__ float smem[];
    float* sA = smem;                    // [64][512] activations
    float* sW = smem + MTILE * ACTSTR;   // [KCL][512] weight tile

    __shared__ float s_c1[NSTEPS], s_isa[NSTEPS], s_sb[NSTEPS];

    int tid = threadIdx.x;
    int cg = tid & 31;
    int rg = tid >> 5;
    int row0 = blockIdx.x * MTILE + rg * 4;

    if (tid == 0) {
        // betas = linspace(1e-4, 0.02, 50), f32; cumprod f32 (matches jnp)
        float acp = 1.0f;
        float bstep = (0.02f - 1e-4f) / 49.0f;
        for (int t = 0; t < NSTEPS; ++t) {
            float beta = fmaf((float)t, bstep, 1e-4f);
            float alpha = 1.0f - beta;
            acp *= alpha;
            s_c1[t]  = beta / sqrtf(1.0f - acp);
            s_isa[t] = 1.0f / sqrtf(alpha);
            s_sb[t]  = sqrtf(beta);
        }
    }

    float xr[4][4];
#pragma unroll
    for (int i = 0; i < 4; ++i)
#pragma unroll
        for (int j = 0; j < 4; ++j)
            xr[i][j] = x_init[(row0 + i) * LAT + cg + 32 * j];

    float tgt = (*tsp) ? 0.0f : 1.0f;   // target column value

    for (int t = NSTEPS - 1; t >= 0; --t) {
        // Build input tile [x | condition]; t_emb/target columns are row-
        // constant and folded into layer-1's bias, so effective K=256.
#pragma unroll
        for (int i = 0; i < 4; ++i) {
            float* arow = sA + (rg * 4 + i) * ACTSTR;
            const float* crow = condition + (row0 + i) * LAT;
#pragma unroll
            for (int j = 0; j < 4; ++j) {
                int c = cg + 32 * j;
                arow[c] = xr[i][j];
                arow[LAT + c] = crow[c];
            }
        }
        float tval = (float)t / (float)NSTEPS;

        {   // layer 1: 256 -> 512, gelu
            float acc[4][16];
#pragma unroll
            for (int j = 0; j < 16; ++j) {
                int c = cg + 32 * j;
                float bb = b1[c] + tval * W1[256 * HID + c] + tgt * W1[257 * HID + c];
                acc[0][j] = bb; acc[1][j] = bb; acc[2][j] = bb; acc[3][j] = bb;
            }
            dense_layer<256, 512, 16>(W1, sA, sW, acc, tid, cg, rg);
            __syncthreads();
#pragma unroll
            for (int i = 0; i < 4; ++i) {
                float* arow = sA + (rg * 4 + i) * ACTSTR;
#pragma unroll
                for (int j = 0; j < 16; ++j)
                    arow[cg + 32 * j] = gelu_exact(acc[i][j]);
            }
        }
        {   // layer 2: 512 -> 512, gelu
            float acc[4][16];
#pragma unroll
            for (int j = 0; j < 16; ++j) {
                float bb = b2[cg + 32 * j];
                acc[0][j] = bb; acc[1][j] = bb; acc[2][j] = bb; acc[3][j] = bb;
            }
            dense_layer<512, 512, 16>(W2, sA, sW, acc, tid, cg, rg);
            __syncthreads();
#pragma unroll
            for (int i = 0; i < 4; ++i) {
                float* arow = sA + (rg * 4 + i) * ACTSTR;
#pragma unroll
                for (int j = 0; j < 16; ++j)
                    arow[cg + 32 * j] = gelu_exact(acc[i][j]);
            }
        }
        {   // layer 3: 512 -> 512, gelu
            float acc[4][16];
#pragma unroll
            for (int j = 0; j < 16; ++j) {
                float bb = b3[cg + 32 * j];
                acc[0][j] = bb; acc[1][j] = bb; acc[2][j] = bb; acc[3][j] = bb;
            }
            dense_layer<512, 512, 16>(W3, sA, sW, acc, tid, cg, rg);
            __syncthreads();
#pragma unroll
            for (int i = 0; i < 4; ++i) {
                float* arow = sA + (rg * 4 + i) * ACTSTR;
#pragma unroll
                for (int j = 0; j < 16; ++j)
                    arow[cg + 32 * j] = gelu_exact(acc[i][j]);
            }
        }
        float np4[4][4];
        {   // layer 4: 512 -> 128, linear
            float acc[4][4];
#pragma unroll
            for (int j = 0; j < 4; ++j) {
                float bb = b4[cg + 32 * j];
                acc[0][j] = bb; acc[1][j] = bb; acc[2][j] = bb; acc[3][j] = bb;
            }
            dense_layer<512, 128, 4>(W4, sA, sW, acc, tid, cg, rg);
            __syncthreads();   // all sA reads done before next step's writes
#pragma unroll
            for (int i = 0; i < 4; ++i)
#pragma unroll
                for (int j = 0; j < 4; ++j)
                    np4[i][j] = acc[i][j];
        }

        // x update with JAX-exact noise (partitionable threefry).
        uint32_t fk0, fk1;
        threefry2x32(0u, 42u, 0u, (uint32_t)t, fk0, fk1);  // fold_in(key(42), t)
        float c1 = s_c1[t], isa = s_isa[t], sb = s_sb[t];
#pragma unroll
        for (int i = 0; i < 4; ++i) {
            int grow = row0 + i;
#pragma unroll
            for (int j = 0; j < 4; ++j) {
                float nz = 0.0f;
                if (t > 0) {
                    uint32_t gi = (uint32_t)(grow * LAT + cg + 32 * j);
                    nz = jax_normal(fk0, fk1, gi);
                }
                xr[i][j] = (xr[i][j] - c1 * np4[i][j]) * isa + sb * nz;
            }
        }
    }

#pragma unroll
    for (int i = 0; i < 4; ++i)
#pragma unroll
        for (int j = 0; j < 4; ++j)
            out[(row0 + i) * LAT + cg + 32 * j] = xr[i][j];
}

extern "C" void kernel_launch(void* const* d_in, const int* in_sizes, int n_in,
                              void* d_out, int out_size) {
    const float* condition = (const float*)d_in[0];
    const float* x_init    = (const float*)d_in[1];
    const float* W1 = (const float*)d_in[2];
    const float* b1 = (const float*)d_in[3];
    const float* W2 = (const float*)d_in[4];
    const float* b2 = (const float*)d_in[5];
    const float* W3 = (const float*)d_in[6];
    const float* b3 = (const float*)d_in[7];
    const float* W4 = (const float*)d_in[8];
    const float* b4 = (const float*)d_in[9];
    const int*   ts = (const int*)d_in[10];
    float* out = (float*)d_out;

    const int smem_bytes = (MTILE * ACTSTR + KCL * HID) * (int)sizeof(float); // 163840
    cudaFuncSetAttribute(diffusion_kernel,
                         cudaFuncAttributeMaxDynamicSharedMemorySize, smem_bytes);
    diffusion_kernel<<<NCTAS, NTHREADS, smem_bytes>>>(
        condition, x_init, W1, b1, W2, b2, W3, b3, W4, b4, ts, out);
}

// round 5
// speedup vs baseline: 5.3494x; 5.3494x over previous
#include <cuda_runtime.h>
#include <cuda_fp16.h>
#include <stdint.h>
#include <math.h>

#define LAT     128
#define HID     512
#define NSTEPS  50
#define NTH     512
#define MT      64
#define NCTAS   128

// strides in halfs (both ≡ 4 words mod 32 -> conflict-free fragment LDS)
#define SA1     264
#define SH      520
#define SWK     40

// SMEM byte offsets
#define SA1_OFF   0               // A1: 64 x 264 halfs  (x | condition), 33792 B
#define SH_OFF    33792           // H:  64 x 520 halfs, 66560 B
#define SW_OFF    100352          // W double buffer: 2 x 512 x 40 halfs
#define SW_BUF    40960
#define SBIAS_OFF 182272          // f32: b1eff[512] b2[512] b3[512] b4[128]
#define SCONST_OFF 188928         // f32: c1[50] isa[50] sqrtbeta[50]
#define SMEM_TOTAL 189952

// fp16 transposed weights WT[n][k] (K contiguous)
#define WT1_OFF 0                 // [512][256]
#define WT2_OFF 131072            // [512][512]
#define WT3_OFF 393216            // [512][512]
#define WT4_OFF 655360            // [128][512]
#define WT_TOT  720896
__device__ __align__(16) __half g_WT[WT_TOT];

// ---------------- PTX helpers ----------------
__device__ __forceinline__ uint32_t smem_u32(const void* p) {
    uint32_t a;
    asm("{ .reg .u64 t; cvta.to.shared.u64 t, %1; cvt.u32.u64 %0, t; }" : "=r"(a) : "l"(p));
    return a;
}
__device__ __forceinline__ void cpasync16(uint32_t dst, const void* src) {
    asm volatile("cp.async.cg.shared.global [%0], [%1], 16;\n" :: "r"(dst), "l"(src));
}
#define CP_COMMIT() asm volatile("cp.async.commit_group;\n" ::: "memory")
#define CP_WAIT0()  asm volatile("cp.async.wait_group 0;\n" ::: "memory")

__device__ __forceinline__ void mma16816(float d[4], const uint32_t a[4], const uint32_t b[2]) {
    asm volatile(
        "mma.sync.aligned.m16n8k16.row.col.f32.f16.f16.f32 "
        "{%0,%1,%2,%3}, {%4,%5,%6,%7}, {%8,%9}, {%0,%1,%2,%3};\n"
        : "+f"(d[0]), "+f"(d[1]), "+f"(d[2]), "+f"(d[3])
        : "r"(a[0]), "r"(a[1]), "r"(a[2]), "r"(a[3]), "r"(b[0]), "r"(b[1]));
}

// ---------------- JAX threefry + erfinv (bit-proven round 2) ----------------
__device__ __forceinline__ uint32_t rotl32(uint32_t x, uint32_t r) {
    return __funnelshift_l(x, x, r);
}
__device__ __forceinline__ void threefry2x32(uint32_t k0, uint32_t k1,
                                             uint32_t c0, uint32_t c1,
                                             uint32_t& o0, uint32_t& o1) {
    uint32_t ks2 = k0 ^ k1 ^ 0x1BD11BDAu;
    uint32_t x0 = c0 + k0, x1 = c1 + k1;
#define TF_RND(r) { x0 += x1; x1 = rotl32(x1, r); x1 ^= x0; }
    TF_RND(13) TF_RND(15) TF_RND(26) TF_RND(6)
    x0 += k1;  x1 += ks2 + 1u;
    TF_RND(17) TF_RND(29) TF_RND(16) TF_RND(24)
    x0 += ks2; x1 += k0 + 2u;
    TF_RND(13) TF_RND(15) TF_RND(26) TF_RND(6)
    x0 += k0;  x1 += k1 + 3u;
    TF_RND(17) TF_RND(29) TF_RND(16) TF_RND(24)
    x0 += k1;  x1 += ks2 + 4u;
    TF_RND(13) TF_RND(15) TF_RND(26) TF_RND(6)
    x0 += ks2; x1 += k0 + 5u;
#undef TF_RND
    o0 = x0; o1 = x1;
}
__device__ __forceinline__ float erfinv_f32(float x) {
    float w = -log1pf(-x * x), p;
    if (w < 5.0f) {
        w -= 2.5f;
        p = 2.81022636e-08f;
        p = fmaf(p, w, 3.43273939e-07f);  p = fmaf(p, w, -3.5233877e-06f);
        p = fmaf(p, w, -4.39150654e-06f); p = fmaf(p, w, 0.00021858087f);
        p = fmaf(p, w, -0.00125372503f);  p = fmaf(p, w, -0.00417768164f);
        p = fmaf(p, w, 0.246640727f);     p = fmaf(p, w, 1.50140941f);
    } else {
        w = sqrtf(w) - 3.0f;
        p = -0.000200214257f;
        p = fmaf(p, w, 0.000100950558f);  p = fmaf(p, w, 0.00134934322f);
        p = fmaf(p, w, -0.00367342844f);  p = fmaf(p, w, 0.00573950773f);
        p = fmaf(p, w, -0.0076224613f);   p = fmaf(p, w, 0.00943887047f);
        p = fmaf(p, w, 1.00167406f);      p = fmaf(p, w, 2.83297682f);
    }
    return p * x;
}
__device__ __forceinline__ float jax_normal(uint32_t fk0, uint32_t fk1, uint32_t gi) {
    uint32_t o0, o1;
    threefry2x32(fk0, fk1, 0u, gi, o0, o1);
    uint32_t bits = o0 ^ o1;
    float f = __uint_as_float((bits >> 9) | 0x3f800000u) - 1.0f;
    float u = fmaxf(fmaf(f, 2.0f, -0.99999994f), -0.99999994f);
    return 1.4142135623730951f * erfinv_f32(u);
}
__device__ __forceinline__ float gelu_exact(float v) {
    return 0.5f * v * (1.0f + erff(v * 0.7071067811865476f));
}

// ---------------- weight prep: fp32 -> fp16 transposed (K contiguous) -------
__global__ void prep_kernel(const float* __restrict__ W1, const float* __restrict__ W2,
                            const float* __restrict__ W3, const float* __restrict__ W4) {
    int i = blockIdx.x * 256 + threadIdx.x;
    if (i < 512*256) { int n=i/256, k=i%256; g_WT[WT1_OFF+i] = __float2half_rn(W1[k*512+n]); return; }
    i -= 512*256;
    if (i < 512*512) { int n=i/512, k=i%512; g_WT[WT2_OFF+i] = __float2half_rn(W2[k*512+n]); return; }
    i -= 512*512;
    if (i < 512*512) { int n=i/512, k=i%512; g_WT[WT3_OFF+i] = __float2half_rn(W3[k*512+n]); return; }
    i -= 512*512;
    if (i < 128*512) { int n=i/512, k=i%512; g_WT[WT4_OFF+i] = __float2half_rn(W4[k*128+n]); return; }
}

// ---------------- one layer: K-chunked, cp.async double-buffered ------------
// Warp computes M=16 rows (m0) x NT*8 cols (n0) via m16n8k16 fragments.
template<int KDIM, int NW, int NT>
__device__ __forceinline__ void layer_mma(char* sm, uint32_t sb,
        const __half* __restrict__ WTg, const __half* A, int sa,
        float (&acc)[NT][4], int tid, int gid, int tig, int m0, int n0)
{
    constexpr int CHUNKS = KDIM / 32;
    // prefetch chunk 0 -> buf 0
    for (int v = tid; v < NW * 4; v += NTH) {
        int n = v >> 2, kp = v & 3;
        cpasync16(sb + SW_OFF + (uint32_t)(n * SWK + kp * 8) * 2,
                  WTg + (size_t)n * KDIM + kp * 8);
    }
    CP_COMMIT();
    for (int c = 0; c < CHUNKS; ++c) {
        CP_WAIT0();
        __syncthreads();
        if (c + 1 < CHUNKS) {
            int bo = ((c + 1) & 1) * SW_BUF;
            const __half* src = WTg + (c + 1) * 32;
            for (int v = tid; v < NW * 4; v += NTH) {
                int n = v >> 2, kp = v & 3;
                cpasync16(sb + SW_OFF + bo + (uint32_t)(n * SWK + kp * 8) * 2,
                          src + (size_t)n * KDIM + kp * 8);
            }
            CP_COMMIT();
        }
        const __half* Wb = (const __half*)(sm + SW_OFF + (c & 1) * SW_BUF);
#pragma unroll
        for (int ks = 0; ks < 2; ++ks) {
            int k0 = c * 32 + ks * 16;
            uint32_t a[4];
            a[0] = *(const uint32_t*)(A + (m0 + gid) * sa + k0 + tig * 2);
            a[1] = *(const uint32_t*)(A + (m0 + gid + 8) * sa + k0 + tig * 2);
            a[2] = *(const uint32_t*)(A + (m0 + gid) * sa + k0 + tig * 2 + 8);
            a[3] = *(const uint32_t*)(A + (m0 + gid + 8) * sa + k0 + tig * 2 + 8);
#pragma unroll
            for (int nt = 0; nt < NT; ++nt) {
                int n = n0 + nt * 8 + gid;
                uint32_t b[2];
                b[0] = *(const uint32_t*)(Wb + n * SWK + ks * 16 + tig * 2);
                b[1] = *(const uint32_t*)(Wb + n * SWK + ks * 16 + tig * 2 + 8);
                mma16816(acc[nt], a, b);
            }
        }
    }
    __syncthreads();   // all A/W reads complete before caller's epilogue writes
}

// epilogue: acc + bias -> gelu -> fp16 H
template<int NT>
__device__ __forceinline__ void epi_gelu(float (&acc)[NT][4], __half* Hout,
                                         const float* bias, int m0, int n0,
                                         int gid, int tig)
{
#pragma unroll
    for (int nt = 0; nt < NT; ++nt) {
        int n = n0 + nt * 8 + tig * 2;
        float2 bb = *(const float2*)(bias + n);
        *(__half2*)(Hout + (m0 + gid) * SH + n) =
            __floats2half2_rn(gelu_exact(acc[nt][0] + bb.x), gelu_exact(acc[nt][1] + bb.y));
        *(__half2*)(Hout + (m0 + gid + 8) * SH + n) =
            __floats2half2_rn(gelu_exact(acc[nt][2] + bb.x), gelu_exact(acc[nt][3] + bb.y));
    }
}

__global__ void __launch_bounds__(NTH, 1)
diffusion_kernel(const float* __restrict__ condition,
                 const float* __restrict__ x_init,
                 const float* __restrict__ W1, const float* __restrict__ b1,
                 const float* __restrict__ b2, const float* __restrict__ b3,
                 const float* __restrict__ b4, const int* __restrict__ tsp,
                 float* __restrict__ out)
{
    extern __shared__ char sm[];
    __half* A1 = (__half*)(sm + SA1_OFF);
    __half* H  = (__half*)(sm + SH_OFF);
    float* sBias = (float*)(sm + SBIAS_OFF);
    float* sC    = (float*)(sm + SCONST_OFF);
    uint32_t sb = smem_u32(sm);

    int tid = threadIdx.x, w = tid >> 5, lane = tid & 31;
    int gid = lane >> 2, tig = lane & 3;
    int m0 = (w & 3) * 16;
    int nL = (w >> 2) * 128;     // layers 1-3 col block
    int n4 = (w >> 2) * 32;      // layer 4 col block
    int mA = m0 + gid, mB = m0 + gid + 8;
    int grA = blockIdx.x * MT + mA, grB = blockIdx.x * MT + mB;

    if (tid == 0) {
        float acp = 1.0f, bstep = (0.02f - 1e-4f) / 49.0f;
        for (int t = 0; t < NSTEPS; ++t) {
            float beta = fmaf((float)t, bstep, 1e-4f);
            float alpha = 1.0f - beta;
            acp *= alpha;
            sC[t]              = beta / sqrtf(1.0f - acp);
            sC[NSTEPS + t]     = 1.0f / sqrtf(alpha);
            sC[2 * NSTEPS + t] = sqrtf(beta);
        }
    }
    sBias[512 + tid]  = b2[tid];
    sBias[1024 + tid] = b3[tid];
    if (tid < 128) sBias[1536 + tid] = b4[tid];

    // x fragment in registers (C-fragment layout); condition -> A1 cols 128..255
    float xr[4][4];
#pragma unroll
    for (int nt = 0; nt < 4; ++nt) {
        int n = n4 + nt * 8 + tig * 2;
        float2 v0 = *(const float2*)(x_init + (size_t)grA * LAT + n);
        float2 v1 = *(const float2*)(x_init + (size_t)grB * LAT + n);
        xr[nt][0] = v0.x; xr[nt][1] = v0.y; xr[nt][2] = v1.x; xr[nt][3] = v1.y;
        float2 c0 = *(const float2*)(condition + (size_t)grA * LAT + n);
        float2 c1 = *(const float2*)(condition + (size_t)grB * LAT + n);
        *(__half2*)(A1 + mA * SA1 + 128 + n) = __floats2half2_rn(c0.x, c0.y);
        *(__half2*)(A1 + mB * SA1 + 128 + n) = __floats2half2_rn(c1.x, c1.y);
    }
    float tgt = (*tsp) ? 0.0f : 1.0f;

    for (int t = NSTEPS - 1; t >= 0; --t) {
        float tval = (float)t / (float)NSTEPS;
        // fold t_emb / target columns into layer-1 bias (fp32 exact)
        sBias[tid] = b1[tid] + tval * W1[256 * HID + tid] + tgt * W1[257 * HID + tid];

        // write x fragment into A1 cols 0..127 (visible after layer1's first sync)
#pragma unroll
        for (int nt = 0; nt < 4; ++nt) {
            int n = n4 + nt * 8 + tig * 2;
            *(__half2*)(A1 + mA * SA1 + n) = __floats2half2_rn(xr[nt][0], xr[nt][1]);
            *(__half2*)(A1 + mB * SA1 + n) = __floats2half2_rn(xr[nt][2], xr[nt][3]);
        }

        float acc[16][4];
#pragma unroll
        for (int i = 0; i < 16; ++i) { acc[i][0]=acc[i][1]=acc[i][2]=acc[i][3]=0.f; }
        layer_mma<256, 512, 16>(sm, sb, g_WT + WT1_OFF, A1, SA1, acc, tid, gid, tig, m0, nL);
        epi_gelu<16>(acc, H, sBias, m0, nL, gid, tig);

#pragma unroll
        for (int i = 0; i < 16; ++i) { acc[i][0]=acc[i][1]=acc[i][2]=acc[i][3]=0.f; }
        layer_mma<512, 512, 16>(sm, sb, g_WT + WT2_OFF, H, SH, acc, tid, gid, tig, m0, nL);
        epi_gelu<16>(acc, H, sBias + 512, m0, nL, gid, tig);

#pragma unroll
        for (int i = 0; i < 16; ++i) { acc[i][0]=acc[i][1]=acc[i][2]=acc[i][3]=0.f; }
        layer_mma<512, 512, 16>(sm, sb, g_WT + WT3_OFF, H, SH, acc, tid, gid, tig, m0, nL);
        epi_gelu<16>(acc, H, sBias + 1024, m0, nL, gid, tig);

        float a4[4][4];
#pragma unroll
        for (int i = 0; i < 4; ++i) { a4[i][0]=a4[i][1]=a4[i][2]=a4[i][3]=0.f; }
        layer_mma<512, 128, 4>(sm, sb, g_WT + WT4_OFF, H, SH, a4, tid, gid, tig, m0, n4);

        // x update with JAX-exact noise
        uint32_t fk0 = 0, fk1 = 0;
        if (t > 0) threefry2x32(0u, 42u, 0u, (uint32_t)t, fk0, fk1);
        float c1 = sC[t], isa = sC[NSTEPS + t], sbeta = sC[2 * NSTEPS + t];
#pragma unroll
        for (int nt = 0; nt < 4; ++nt) {
            int n = n4 + nt * 8 + tig * 2;
            float2 bb = *(const float2*)(sBias + 1536 + n);
            float np0 = a4[nt][0] + bb.x, np1 = a4[nt][1] + bb.y;
            float np2 = a4[nt][2] + bb.x, np3 = a4[nt][3] + bb.y;
            float z0=0.f, z1=0.f, z2=0.f, z3=0.f;
            if (t > 0) {
                z0 = jax_normal(fk0, fk1, (uint32_t)(grA * LAT + n));
                z1 = jax_normal(fk0, fk1, (uint32_t)(grA * LAT + n + 1));
                z2 = jax_normal(fk0, fk1, (uint32_t)(grB * LAT + n));
                z3 = jax_normal(fk0, fk1, (uint32_t)(grB * LAT + n + 1));
            }
            xr[nt][0] = (xr[nt][0] - c1 * np0) * isa + sbeta * z0;
            xr[nt][1] = (xr[nt][1] - c1 * np1) * isa + sbeta * z1;
            xr[nt][2] = (xr[nt][2] - c1 * np2) * isa + sbeta * z2;
            xr[nt][3] = (xr[nt][3] - c1 * np3) * isa + sbeta * z3;
        }
        __syncthreads();   // A1 x-region reads (layer1) done before next write
    }

#pragma unroll
    for (int nt = 0; nt < 4; ++nt) {
        int n = n4 + nt * 8 + tig * 2;
        *(float2*)(out + (size_t)grA * LAT + n) = make_float2(xr[nt][0], xr[nt][1]);
        *(float2*)(out + (size_t)grB * LAT + n) = make_float2(xr[nt][2], xr[nt][3]);
    }
}

extern "C" void kernel_launch(void* const* d_in, const int* in_sizes, int n_in,
                              void* d_out, int out_size) {
    const float* condition = (const float*)d_in[0];
    const float* x_init    = (const float*)d_in[1];
    const float* W1 = (const float*)d_in[2];
    const float* b1 = (const float*)d_in[3];
    const float* W2 = (const float*)d_in[4];
    const float* b2 = (const float*)d_in[5];
    const float* W3 = (const float*)d_in[6];
    const float* b3 = (const float*)d_in[7];
    const float* W4 = (const float*)d_in[8];
    const float* b4 = (const float*)d_in[9];
    const int*   ts = (const int*)d_in[10];
    float* out = (float*)d_out;

    prep_kernel<<<(WT_TOT + 255) / 256, 256>>>(W1, W2, W3, W4);

    cudaFuncSetAttribute(diffusion_kernel,
                         cudaFuncAttributeMaxDynamicSharedMemorySize, SMEM_TOTAL);
    diffusion_kernel<<<NCTAS, NTH, SMEM_TOTAL>>>(
        condition, x_init, W1, b1, b2, b3, b4, ts, out);
}